// round 1
// baseline (speedup 1.0000x reference)
#include <cuda_runtime.h>
#include <math.h>

#define Bq 4
#define Sq 4096
#define Dq 1024
#define Nq 16
#define Mq (Bq*Sq)      /* 16384 rows */
#define Kq Dq           /* 1024 */
#define NCAT 2080       /* 1024 (Wd) + 1024 (WD) + 16 (Wb) + 16 (Wc) */

/* ---- scratch (static __device__, per allocation rules) ---- */
__device__ float g_h[Mq * Dq];       /* layernorm output           64 MB */
__device__ float g_delta[Mq * Dq];   /* softplus(h Wd^T + bd)      64 MB */
__device__ float g_lin[Mq * Dq];     /* h WD^T + bD                64 MB */
__device__ float g_Bc[Mq * Nq];      /* h Wb^T + bb                 1 MB */
__device__ float g_Cc[Mq * Nq];      /* h Wc^T + bc                 1 MB */
__device__ float g_Wcat[NCAT * Kq];  /* concatenated weights      8.5 MB */
__device__ float g_bcat[NCAT];
__device__ float g_A2[Dq * Nq];      /* -exp(log_A) * log2(e) */

/* ---------------- prep: build Wcat / bcat / A2 ---------------- */
__global__ void prep_kernel(const float* __restrict__ logA,
                            const float* __restrict__ Wd, const float* __restrict__ bd,
                            const float* __restrict__ Wb, const float* __restrict__ bb,
                            const float* __restrict__ Wc, const float* __restrict__ bc,
                            const float* __restrict__ WD, const float* __restrict__ bD)
{
    int r = blockIdx.x;          /* 0..2079 */
    int tid = threadIdx.x;       /* 256 threads, 1024 floats/row -> float4 each */
    const float* src;
    if (r < 1024)        src = Wd + (size_t)r * Kq;
    else if (r < 2048)   src = WD + (size_t)(r - 1024) * Kq;
    else if (r < 2064)   src = Wb + (size_t)(r - 2048) * Kq;
    else                 src = Wc + (size_t)(r - 2064) * Kq;
    float4 v = reinterpret_cast<const float4*>(src)[tid];
    reinterpret_cast<float4*>(g_Wcat + (size_t)r * Kq)[tid] = v;

    if (tid == 0) {
        float bv;
        if (r < 1024)      bv = bd[r];
        else if (r < 2048) bv = bD[r - 1024];
        else if (r < 2064) bv = bb[r - 2048];
        else               bv = bc[r - 2064];
        g_bcat[r] = bv;
    }
    if (r < Dq && tid < Nq) {
        g_A2[r * Nq + tid] = -expf(logA[r * Nq + tid]) * 1.44269504088896340736f;
    }
}

/* ---------------- layernorm: one block per row ---------------- */
__global__ void ln_kernel(const float* __restrict__ x,
                          const float* __restrict__ w,
                          const float* __restrict__ b)
{
    int row = blockIdx.x;        /* 0..16383 */
    int tid = threadIdx.x;       /* 256 */
    const float4* x4 = reinterpret_cast<const float4*>(x) + (size_t)row * 256;
    float4 v = x4[tid];
    float sum = v.x + v.y + v.z + v.w;
    float sq  = v.x*v.x + v.y*v.y + v.z*v.z + v.w*v.w;

    #pragma unroll
    for (int o = 16; o > 0; o >>= 1) {
        sum += __shfl_down_sync(0xffffffffu, sum, o);
        sq  += __shfl_down_sync(0xffffffffu, sq, o);
    }
    __shared__ float red0[8], red1[8];
    int warp = tid >> 5, lane = tid & 31;
    if (lane == 0) { red0[warp] = sum; red1[warp] = sq; }
    __syncthreads();
    if (tid < 32) {
        float s1 = (tid < 8) ? red0[tid] : 0.f;
        float s2 = (tid < 8) ? red1[tid] : 0.f;
        #pragma unroll
        for (int o = 4; o > 0; o >>= 1) {
            s1 += __shfl_down_sync(0xffffffffu, s1, o);
            s2 += __shfl_down_sync(0xffffffffu, s2, o);
        }
        if (tid == 0) { red0[0] = s1; red1[0] = s2; }
    }
    __syncthreads();
    float mean = red0[0] * (1.0f / Dq);
    float var  = red1[0] * (1.0f / Dq) - mean * mean;
    float rs   = rsqrtf(var + 1e-5f);

    float4 wv = reinterpret_cast<const float4*>(w)[tid];
    float4 bv = reinterpret_cast<const float4*>(b)[tid];
    float4 o;
    o.x = (v.x - mean) * rs * wv.x + bv.x;
    o.y = (v.y - mean) * rs * wv.y + bv.y;
    o.z = (v.z - mean) * rs * wv.z + bv.z;
    o.w = (v.w - mean) * rs * wv.w + bv.w;
    reinterpret_cast<float4*>(g_h)[(size_t)row * 256 + tid] = o;
}

/* ------------- fused SGEMM: C = h @ Wcat^T, routed epilogue ------------- */
#define BM 128
#define BN 128
#define BK 16

__global__ __launch_bounds__(256)
void sgemm_kernel()
{
    __shared__ float As[BK][BM];
    __shared__ float Bs[BK][BN];

    int n0 = blockIdx.x * BN;
    int m0 = blockIdx.y * BM;
    int tid = threadIdx.x;
    int tx = tid & 15, ty = tid >> 4;

    float acc[8][8];
    #pragma unroll
    for (int i = 0; i < 8; i++)
        #pragma unroll
        for (int j = 0; j < 8; j++) acc[i][j] = 0.f;

    int lr = tid >> 2;           /* 0..63 */
    int lc = (tid & 3) << 2;     /* 0,4,8,12 */

    for (int k0 = 0; k0 < Kq; k0 += BK) {
        #pragma unroll
        for (int i = 0; i < 2; i++) {
            int r = lr + i * 64;
            float4 av = *reinterpret_cast<const float4*>(g_h + (size_t)(m0 + r) * Kq + k0 + lc);
            As[lc + 0][r] = av.x; As[lc + 1][r] = av.y;
            As[lc + 2][r] = av.z; As[lc + 3][r] = av.w;
            int nn = n0 + r;
            float4 bvv = make_float4(0.f, 0.f, 0.f, 0.f);
            if (nn < NCAT)
                bvv = *reinterpret_cast<const float4*>(g_Wcat + (size_t)nn * Kq + k0 + lc);
            Bs[lc + 0][r] = bvv.x; Bs[lc + 1][r] = bvv.y;
            Bs[lc + 2][r] = bvv.z; Bs[lc + 3][r] = bvv.w;
        }
        __syncthreads();

        #pragma unroll
        for (int k = 0; k < BK; k++) {
            float a[8], bq[8];
            *reinterpret_cast<float4*>(&a[0]) = *reinterpret_cast<const float4*>(&As[k][ty * 4]);
            *reinterpret_cast<float4*>(&a[4]) = *reinterpret_cast<const float4*>(&As[k][64 + ty * 4]);
            *reinterpret_cast<float4*>(&bq[0]) = *reinterpret_cast<const float4*>(&Bs[k][tx * 4]);
            *reinterpret_cast<float4*>(&bq[4]) = *reinterpret_cast<const float4*>(&Bs[k][64 + tx * 4]);
            #pragma unroll
            for (int i = 0; i < 8; i++)
                #pragma unroll
                for (int j = 0; j < 8; j++)
                    acc[i][j] = fmaf(a[i], bq[j], acc[i][j]);
        }
        __syncthreads();
    }

    /* routed epilogue */
    #pragma unroll
    for (int i = 0; i < 8; i++) {
        int m = m0 + ((i < 4) ? (ty * 4 + i) : (64 + ty * 4 + i - 4));
        #pragma unroll
        for (int j = 0; j < 8; j++) {
            int col = n0 + ((j < 4) ? (tx * 4 + j) : (64 + tx * 4 + j - 4));
            if (col >= NCAT) continue;
            float v = acc[i][j] + g_bcat[col];
            if (col < 1024) {
                /* softplus, stable */
                float sp = fmaxf(v, 0.f) + log1pf(expf(-fabsf(v)));
                g_delta[(size_t)m * Dq + col] = sp;
            } else if (col < 2048) {
                g_lin[(size_t)m * Dq + (col - 1024)] = v;
            } else if (col < 2064) {
                g_Bc[(size_t)m * Nq + (col - 2048)] = v;
            } else {
                g_Cc[(size_t)m * Nq + (col - 2064)] = v;
            }
        }
    }
}

/* ------------- selective scan + residual; thread = (b, d, n) ------------- */
__global__ __launch_bounds__(256)
void scan_kernel(const float* __restrict__ xin, float* __restrict__ out)
{
    int b    = blockIdx.y;          /* 0..3 */
    int dblk = blockIdx.x;          /* 0..63 */
    int tid  = threadIdx.x;         /* 256 = 16 d x 16 n */
    int n    = tid & 15;
    int td   = tid >> 4;
    int d    = dblk * 16 + td;

    float a2 = g_A2[d * Nq + n];
    float s  = 0.f;

    int idx  = (b * Sq) * Dq + d;
    int nidx = (b * Sq) * Nq + n;

    /* depth-1 prefetch of all streamed operands */
    float dt = g_delta[idx];
    float hh = g_h[idx];
    float bn = g_Bc[nidx];
    float cn = g_Cc[nidx];
    float xx = xin[idx];
    float ll = g_lin[idx];

    for (int t = 0; t < Sq; t++) {
        float dt1 = 0.f, hh1 = 0.f, bn1 = 0.f, cn1 = 0.f, xx1 = 0.f, ll1 = 0.f;
        int idx1 = idx + Dq, nidx1 = nidx + Nq;
        if (t < Sq - 1) {
            dt1 = g_delta[idx1];
            hh1 = g_h[idx1];
            bn1 = g_Bc[nidx1];
            cn1 = g_Cc[nidx1];
            xx1 = xin[idx1];
            ll1 = g_lin[idx1];
        }

        float dA = exp2f(dt * a2);                 /* exp(dt * A[d][n]) */
        s = fmaf(dA, s, dt * hh * bn);
        float p = s * cn;
        p += __shfl_xor_sync(0xffffffffu, p, 1);
        p += __shfl_xor_sync(0xffffffffu, p, 2);
        p += __shfl_xor_sync(0xffffffffu, p, 4);
        p += __shfl_xor_sync(0xffffffffu, p, 8);
        if (n == 0) out[idx] = xx + ll + p;

        dt = dt1; hh = hh1; bn = bn1; cn = cn1; xx = xx1; ll = ll1;
        idx = idx1; nidx = nidx1;
    }
}

/* ------------------------------- launch ------------------------------- */
extern "C" void kernel_launch(void* const* d_in, const int* in_sizes, int n_in,
                              void* d_out, int out_size)
{
    const float* x    = (const float*)d_in[0];
    const float* logA = (const float*)d_in[1];
    const float* Wd   = (const float*)d_in[2];
    const float* bd   = (const float*)d_in[3];
    const float* Wb   = (const float*)d_in[4];
    const float* bb   = (const float*)d_in[5];
    const float* Wc   = (const float*)d_in[6];
    const float* bc   = (const float*)d_in[7];
    const float* WDp  = (const float*)d_in[8];
    const float* bD   = (const float*)d_in[9];
    const float* lnw  = (const float*)d_in[10];
    const float* lnb  = (const float*)d_in[11];
    float* out = (float*)d_out;

    prep_kernel<<<NCAT, 256>>>(logA, Wd, bd, Wb, bb, Wc, bc, WDp, bD);
    ln_kernel<<<Mq, 256>>>(x, lnw, lnb);
    dim3 ggrid((NCAT + BN - 1) / BN, Mq / BM);   /* 17 x 128 */
    sgemm_kernel<<<ggrid, 256>>>();
    dim3 sgrid(Dq / 16, Bq);                     /* 64 x 4 */
    scan_kernel<<<sgrid, 256>>>(x, out);
}

// round 3
// speedup vs baseline: 1.7738x; 1.7738x over previous
#include <cuda_runtime.h>
#include <cuda_bf16.h>
#include <math.h>
#include <stdint.h>

#define Bq 4
#define Sq 4096
#define Dq 1024
#define Nq 16
#define Mq (Bq*Sq)      /* 16384 rows */
#define Kq Dq           /* 1024 */
#define NCAT 2080       /* 1024 (Wd) + 1024 (WD) + 16 (Wb) + 16 (Wc) */
#define NPAD 2176       /* padded to 17*128 */

/* ---- scratch (static __device__, per allocation rules) ---- */
__device__ float g_h[Mq * Dq];
__device__ float g_delta[Mq * Dq];
__device__ float g_lin[Mq * Dq];
__device__ float g_Bc[Mq * Nq];
__device__ float g_Cc[Mq * Nq];
__device__ float g_bcat[NPAD];
__device__ float g_A2[Dq * Nq];
__device__ __nv_bfloat16 g_h_hi[Mq * Kq];
__device__ __nv_bfloat16 g_h_lo[Mq * Kq];
__device__ __nv_bfloat16 g_W_hi[NPAD * Kq];
__device__ __nv_bfloat16 g_W_lo[NPAD * Kq];

__device__ __forceinline__ uint32_t smem_u32(const void* p) {
    uint32_t r;
    asm("{ .reg .u64 t; cvta.to.shared.u64 t, %1; cvt.u32.u64 %0, t; }" : "=r"(r) : "l"(p));
    return r;
}

/* ---------------- prep: bf16-split weights + bias + A2 ---------------- */
__global__ void prep_kernel(const float* __restrict__ logA,
                            const float* __restrict__ Wd, const float* __restrict__ bd,
                            const float* __restrict__ Wb, const float* __restrict__ bb,
                            const float* __restrict__ Wc, const float* __restrict__ bc,
                            const float* __restrict__ WD, const float* __restrict__ bD)
{
    int r = blockIdx.x;          /* 0..2175 */
    int tid = threadIdx.x;       /* 256 */
    const float* src = 0;
    if (r < 1024)        src = Wd + (size_t)r * Kq;
    else if (r < 2048)   src = WD + (size_t)(r - 1024) * Kq;
    else if (r < 2064)   src = Wb + (size_t)(r - 2048) * Kq;
    else if (r < NCAT)   src = Wc + (size_t)(r - 2064) * Kq;

    float4 v = src ? reinterpret_cast<const float4*>(src)[tid]
                   : make_float4(0.f, 0.f, 0.f, 0.f);
    __nv_bfloat16 hi[4], lo[4];
    float vv[4] = {v.x, v.y, v.z, v.w};
    #pragma unroll
    for (int i = 0; i < 4; i++) {
        hi[i] = __float2bfloat16(vv[i]);
        lo[i] = __float2bfloat16(vv[i] - __bfloat162float(hi[i]));
    }
    *reinterpret_cast<uint2*>(g_W_hi + (size_t)r * Kq + tid * 4) = *reinterpret_cast<uint2*>(hi);
    *reinterpret_cast<uint2*>(g_W_lo + (size_t)r * Kq + tid * 4) = *reinterpret_cast<uint2*>(lo);

    if (tid == 0) {
        float bv = 0.f;
        if (r < 1024)      bv = bd[r];
        else if (r < 2048) bv = bD[r - 1024];
        else if (r < 2064) bv = bb[r - 2048];
        else if (r < NCAT) bv = bc[r - 2064];
        g_bcat[r] = bv;
    }
    if (r < Dq && tid < Nq) {
        g_A2[r * Nq + tid] = -expf(logA[r * Nq + tid]) * 1.44269504088896340736f;
    }
}

/* ---------------- layernorm: one block per row, emits fp32 + bf16 hi/lo ---------------- */
__global__ void ln_kernel(const float* __restrict__ x,
                          const float* __restrict__ w,
                          const float* __restrict__ b)
{
    int row = blockIdx.x;
    int tid = threadIdx.x;       /* 256 */
    const float4* x4 = reinterpret_cast<const float4*>(x) + (size_t)row * 256;
    float4 v = x4[tid];
    float sum = v.x + v.y + v.z + v.w;
    float sq  = v.x*v.x + v.y*v.y + v.z*v.z + v.w*v.w;

    #pragma unroll
    for (int o = 16; o > 0; o >>= 1) {
        sum += __shfl_down_sync(0xffffffffu, sum, o);
        sq  += __shfl_down_sync(0xffffffffu, sq, o);
    }
    __shared__ float red0[8], red1[8];
    int warp = tid >> 5, lane = tid & 31;
    if (lane == 0) { red0[warp] = sum; red1[warp] = sq; }
    __syncthreads();
    if (tid < 32) {
        float s1 = (tid < 8) ? red0[tid] : 0.f;
        float s2 = (tid < 8) ? red1[tid] : 0.f;
        #pragma unroll
        for (int o = 4; o > 0; o >>= 1) {
            s1 += __shfl_down_sync(0xffffffffu, s1, o);
            s2 += __shfl_down_sync(0xffffffffu, s2, o);
        }
        if (tid == 0) { red0[0] = s1; red1[0] = s2; }
    }
    __syncthreads();
    float mean = red0[0] * (1.0f / Dq);
    float var  = red1[0] * (1.0f / Dq) - mean * mean;
    float rs   = rsqrtf(var + 1e-5f);

    float4 wv = reinterpret_cast<const float4*>(w)[tid];
    float4 bv = reinterpret_cast<const float4*>(b)[tid];
    float4 o;
    o.x = (v.x - mean) * rs * wv.x + bv.x;
    o.y = (v.y - mean) * rs * wv.y + bv.y;
    o.z = (v.z - mean) * rs * wv.z + bv.z;
    o.w = (v.w - mean) * rs * wv.w + bv.w;
    reinterpret_cast<float4*>(g_h)[(size_t)row * 256 + tid] = o;

    __nv_bfloat16 hi[4], lo[4];
    float vv[4] = {o.x, o.y, o.z, o.w};
    #pragma unroll
    for (int i = 0; i < 4; i++) {
        hi[i] = __float2bfloat16(vv[i]);
        lo[i] = __float2bfloat16(vv[i] - __bfloat162float(hi[i]));
    }
    *reinterpret_cast<uint2*>(g_h_hi + (size_t)row * Kq + tid * 4) = *reinterpret_cast<uint2*>(hi);
    *reinterpret_cast<uint2*>(g_h_lo + (size_t)row * Kq + tid * 4) = *reinterpret_cast<uint2*>(lo);
}

/* =========== HMMA GEMM: C = h @ Wcat^T (bf16 3-term split) ============ */
/* 128x128 tile, BK=16, double-buffered cp.async, 8 warps (4m x 2n).      */
#define BKg 16
#define SROW 24          /* padded row stride in bf16 (48B, 16B-aligned) */
#define NCHK (Kq / BKg)  /* 64 */

/* sm[buf][A=0/B=1][hi=0/lo=1][128][SROW] */
__shared__ __nv_bfloat16 sm_tiles_dummy_decl; /* (placeholder, real decl inside kernel) */

__device__ __forceinline__ void cp16(uint32_t dst, const void* src) {
    asm volatile("cp.async.cg.shared.global [%0], [%1], 16;" :: "r"(dst), "l"(src) : "memory");
}
__device__ __forceinline__ void cp_commit() {
    asm volatile("cp.async.commit_group;" ::: "memory");
}
template<int N> __device__ __forceinline__ void cp_wait() {
    asm volatile("cp.async.wait_group %0;" :: "n"(N) : "memory");
}
__device__ __forceinline__ void ldm_x4(uint32_t addr, uint32_t* r) {
    asm volatile("ldmatrix.sync.aligned.m8n8.x4.shared.b16 {%0,%1,%2,%3}, [%4];"
                 : "=r"(r[0]), "=r"(r[1]), "=r"(r[2]), "=r"(r[3]) : "r"(addr));
}
__device__ __forceinline__ void mma_bf16(float* c, const uint32_t* a, const uint32_t* b) {
    asm volatile("mma.sync.aligned.m16n8k16.row.col.f32.bf16.bf16.f32 "
                 "{%0,%1,%2,%3}, {%4,%5,%6,%7}, {%8,%9}, {%0,%1,%2,%3};"
                 : "+f"(c[0]), "+f"(c[1]), "+f"(c[2]), "+f"(c[3])
                 : "r"(a[0]), "r"(a[1]), "r"(a[2]), "r"(a[3]), "r"(b[0]), "r"(b[1]));
}
__device__ __forceinline__ float softplus_f(float v) {
    return fmaxf(v, 0.f) + log1pf(expf(-fabsf(v)));
}

__global__ __launch_bounds__(256, 1)
void gemm_hmma_kernel()
{
    __shared__ __align__(16) __nv_bfloat16 sm[2][2][2][128][SROW];  /* 48KB */

    int tid  = threadIdx.x;
    int wid  = tid >> 5, lane = tid & 31;
    int n0   = blockIdx.x * 128;
    int m0   = blockIdx.y * 128;
    int wm   = wid >> 1;           /* 0..3 -> m offset 32*wm */
    int wn   = wid & 1;            /* 0..1 -> n offset 64*wn */

    uint32_t smb = smem_u32(&sm[0][0][0][0][0]);
    #define SOFF(buf, ab, p, row) ((uint32_t)(((((buf)*2 + (ab))*2 + (p))*128 + (row)) * (SROW*2)))

    /* per-thread load slots: row = tid/2 (0..127), chunk c = tid&1 (16B each) */
    int lrow = tid >> 1, lc = tid & 1;
    const __nv_bfloat16* srcA_hi = g_h_hi + (size_t)(m0 + lrow) * Kq + lc * 8;
    const __nv_bfloat16* srcA_lo = g_h_lo + (size_t)(m0 + lrow) * Kq + lc * 8;
    const __nv_bfloat16* srcB_hi = g_W_hi + (size_t)(n0 + lrow) * Kq + lc * 8;
    const __nv_bfloat16* srcB_lo = g_W_lo + (size_t)(n0 + lrow) * Kq + lc * 8;
    uint32_t dst_off = (uint32_t)(lrow * (SROW*2) + lc * 16);

    float acc[2][8][4];
    #pragma unroll
    for (int i = 0; i < 2; i++)
        #pragma unroll
        for (int j = 0; j < 8; j++)
            #pragma unroll
            for (int k = 0; k < 4; k++) acc[i][j][k] = 0.f;

    /* prologue: stage 0 */
    {
        cp16(smb + SOFF(0,0,0,0) + dst_off, srcA_hi);
        cp16(smb + SOFF(0,0,1,0) + dst_off, srcA_lo);
        cp16(smb + SOFF(0,1,0,0) + dst_off, srcB_hi);
        cp16(smb + SOFF(0,1,1,0) + dst_off, srcB_lo);
        cp_commit();
    }

    /* ldmatrix address components (within one [128][SROW] plane) */
    int a_row = wm * 32 + (lane & 15);
    uint32_t a_bo = (uint32_t)((lane >> 4) * 16);
    int b_rowbase = wn * 64 + (lane & 7) + ((lane >> 4) * 8);
    uint32_t b_bo = (uint32_t)(((lane >> 3) & 1) * 16);

    for (int kc = 0; kc < NCHK; kc++) {
        int buf = kc & 1;
        if (kc + 1 < NCHK) {
            int nb = (kc + 1) & 1;
            size_t go = (size_t)(kc + 1) * BKg;
            cp16(smb + SOFF(nb,0,0,0) + dst_off, srcA_hi + go);
            cp16(smb + SOFF(nb,0,1,0) + dst_off, srcA_lo + go);
            cp16(smb + SOFF(nb,1,0,0) + dst_off, srcB_hi + go);
            cp16(smb + SOFF(nb,1,1,0) + dst_off, srcB_lo + go);
            cp_commit();
            cp_wait<1>();
        } else {
            cp_wait<0>();
        }
        __syncthreads();

        uint32_t aH[2][4], aL[2][4], bH[8][2], bL[8][2];
        #pragma unroll
        for (int mt = 0; mt < 2; mt++) {
            int row = a_row + mt * 16;
            ldm_x4(smb + SOFF(buf,0,0,row) + a_bo, aH[mt]);
            ldm_x4(smb + SOFF(buf,0,1,row) + a_bo, aL[mt]);
        }
        #pragma unroll
        for (int p = 0; p < 4; p++) {
            int row = b_rowbase + p * 16;
            uint32_t r4[4];
            ldm_x4(smb + SOFF(buf,1,0,row) + b_bo, r4);
            bH[2*p][0] = r4[0]; bH[2*p][1] = r4[1];
            bH[2*p+1][0] = r4[2]; bH[2*p+1][1] = r4[3];
            ldm_x4(smb + SOFF(buf,1,1,row) + b_bo, r4);
            bL[2*p][0] = r4[0]; bL[2*p][1] = r4[1];
            bL[2*p+1][0] = r4[2]; bL[2*p+1][1] = r4[3];
        }

        #pragma unroll
        for (int mt = 0; mt < 2; mt++)
            #pragma unroll
            for (int nt = 0; nt < 8; nt++)
                mma_bf16(acc[mt][nt], aH[mt], bH[nt]);
        #pragma unroll
        for (int mt = 0; mt < 2; mt++)
            #pragma unroll
            for (int nt = 0; nt < 8; nt++)
                mma_bf16(acc[mt][nt], aH[mt], bL[nt]);
        #pragma unroll
        for (int mt = 0; mt < 2; mt++)
            #pragma unroll
            for (int nt = 0; nt < 8; nt++)
                mma_bf16(acc[mt][nt], aL[mt], bH[nt]);

        __syncthreads();
    }

    /* epilogue: routed stores with bias (+softplus for delta cols) */
    int qrow = lane >> 2;            /* 0..7 */
    int qcol = (lane & 3) * 2;
    #pragma unroll
    for (int mt = 0; mt < 2; mt++) {
        #pragma unroll
        for (int half = 0; half < 2; half++) {
            int m = m0 + wm * 32 + mt * 16 + qrow + half * 8;
            #pragma unroll
            for (int nt = 0; nt < 8; nt++) {
                int col = n0 + wn * 64 + nt * 8 + qcol;
                if (col >= NCAT) continue;
                float v0 = acc[mt][nt][half * 2 + 0] + g_bcat[col];
                float v1 = acc[mt][nt][half * 2 + 1] + g_bcat[col + 1];
                if (col < 1024) {
                    float2 o = make_float2(softplus_f(v0), softplus_f(v1));
                    *reinterpret_cast<float2*>(g_delta + (size_t)m * Dq + col) = o;
                } else if (col < 2048) {
                    *reinterpret_cast<float2*>(g_lin + (size_t)m * Dq + (col - 1024)) =
                        make_float2(v0, v1);
                } else if (col < 2064) {
                    *reinterpret_cast<float2*>(g_Bc + (size_t)m * Nq + (col - 2048)) =
                        make_float2(v0, v1);
                } else {
                    *reinterpret_cast<float2*>(g_Cc + (size_t)m * Nq + (col - 2064)) =
                        make_float2(v0, v1);
                }
            }
        }
    }
}

/* ------------- selective scan + residual; thread = (b, d, n) ------------- */
__global__ __launch_bounds__(256)
void scan_kernel(const float* __restrict__ xin, float* __restrict__ out)
{
    int b    = blockIdx.y;
    int dblk = blockIdx.x;
    int tid  = threadIdx.x;         /* 256 = 16 d x 16 n */
    int n    = tid & 15;
    int td   = tid >> 4;
    int d    = dblk * 16 + td;

    float a2 = g_A2[d * Nq + n];
    float s  = 0.f;

    int idx  = (b * Sq) * Dq + d;
    int nidx = (b * Sq) * Nq + n;

    float dt = g_delta[idx];
    float hh = g_h[idx];
    float bn = g_Bc[nidx];
    float cn = g_Cc[nidx];
    float xx = xin[idx];
    float ll = g_lin[idx];

    for (int t = 0; t < Sq; t++) {
        float dt1 = 0.f, hh1 = 0.f, bn1 = 0.f, cn1 = 0.f, xx1 = 0.f, ll1 = 0.f;
        int idx1 = idx + Dq, nidx1 = nidx + Nq;
        if (t < Sq - 1) {
            dt1 = g_delta[idx1];
            hh1 = g_h[idx1];
            bn1 = g_Bc[nidx1];
            cn1 = g_Cc[nidx1];
            xx1 = xin[idx1];
            ll1 = g_lin[idx1];
        }

        float dA = exp2f(dt * a2);
        s = fmaf(dA, s, dt * hh * bn);
        float p = s * cn;
        p += __shfl_xor_sync(0xffffffffu, p, 1);
        p += __shfl_xor_sync(0xffffffffu, p, 2);
        p += __shfl_xor_sync(0xffffffffu, p, 4);
        p += __shfl_xor_sync(0xffffffffu, p, 8);
        if (n == 0) out[idx] = xx + ll + p;

        dt = dt1; hh = hh1; bn = bn1; cn = cn1; xx = xx1; ll = ll1;
        idx = idx1; nidx = nidx1;
    }
}

/* ------------------------------- launch ------------------------------- */
extern "C" void kernel_launch(void* const* d_in, const int* in_sizes, int n_in,
                              void* d_out, int out_size)
{
    const float* x    = (const float*)d_in[0];
    const float* logA = (const float*)d_in[1];
    const float* Wd   = (const float*)d_in[2];
    const float* bd   = (const float*)d_in[3];
    const float* Wb   = (const float*)d_in[4];
    const float* bb   = (const float*)d_in[5];
    const float* Wc   = (const float*)d_in[6];
    const float* bc   = (const float*)d_in[7];
    const float* WDp  = (const float*)d_in[8];
    const float* bD   = (const float*)d_in[9];
    const float* lnw  = (const float*)d_in[10];
    const float* lnb  = (const float*)d_in[11];
    float* out = (float*)d_out;

    prep_kernel<<<NPAD, 256>>>(logA, Wd, bd, Wb, bb, Wc, bc, WDp, bD);
    ln_kernel<<<Mq, 256>>>(x, lnw, lnb);
    dim3 ggrid(NPAD / 128, Mq / 128);            /* 17 x 128 */
    gemm_hmma_kernel<<<ggrid, 256>>>();
    dim3 sgrid(Dq / 16, Bq);                     /* 64 x 4 */
    scan_kernel<<<sgrid, 256>>>(x, out);
}

// round 4
// speedup vs baseline: 1.9354x; 1.0911x over previous
#include <cuda_runtime.h>
#include <cuda_bf16.h>
#include <math.h>
#include <stdint.h>

#define Bq 4
#define Sq 4096
#define Dq 1024
#define Nq 16
#define Mq (Bq*Sq)      /* 16384 rows */
#define Kq Dq           /* 1024 */
#define NCAT 2080
#define NPAD 2176       /* 17*128 */

/* ---- scratch ---- */
__device__ float g_h[Mq * Dq];
__device__ float g_delta[Mq * Dq];
__device__ float g_lin[Mq * Dq];
__device__ float g_Bc[Mq * Nq];
__device__ float g_Cc[Mq * Nq];
__device__ float g_bcat[NPAD];
__device__ float g_A2[Dq * Nq];
__device__ __nv_bfloat16 g_h_hi[Mq * Kq];
__device__ __nv_bfloat16 g_h_lo[Mq * Kq];
__device__ __nv_bfloat16 g_W_hi[NPAD * Kq];
__device__ __nv_bfloat16 g_W_lo[NPAD * Kq];

__device__ __forceinline__ uint32_t smem_u32(const void* p) {
    uint32_t r;
    asm("{ .reg .u64 t; cvta.to.shared.u64 t, %1; cvt.u32.u64 %0, t; }" : "=r"(r) : "l"(p));
    return r;
}

/* ---------------- prep ---------------- */
__global__ void prep_kernel(const float* __restrict__ logA,
                            const float* __restrict__ Wd, const float* __restrict__ bd,
                            const float* __restrict__ Wb, const float* __restrict__ bb,
                            const float* __restrict__ Wc, const float* __restrict__ bc,
                            const float* __restrict__ WD, const float* __restrict__ bD)
{
    int r = blockIdx.x;
    int tid = threadIdx.x;
    const float* src = 0;
    if (r < 1024)        src = Wd + (size_t)r * Kq;
    else if (r < 2048)   src = WD + (size_t)(r - 1024) * Kq;
    else if (r < 2064)   src = Wb + (size_t)(r - 2048) * Kq;
    else if (r < NCAT)   src = Wc + (size_t)(r - 2064) * Kq;

    float4 v = src ? reinterpret_cast<const float4*>(src)[tid]
                   : make_float4(0.f, 0.f, 0.f, 0.f);
    __nv_bfloat16 hi[4], lo[4];
    float vv[4] = {v.x, v.y, v.z, v.w};
    #pragma unroll
    for (int i = 0; i < 4; i++) {
        hi[i] = __float2bfloat16(vv[i]);
        lo[i] = __float2bfloat16(vv[i] - __bfloat162float(hi[i]));
    }
    *reinterpret_cast<uint2*>(g_W_hi + (size_t)r * Kq + tid * 4) = *reinterpret_cast<uint2*>(hi);
    *reinterpret_cast<uint2*>(g_W_lo + (size_t)r * Kq + tid * 4) = *reinterpret_cast<uint2*>(lo);

    if (tid == 0) {
        float bv = 0.f;
        if (r < 1024)      bv = bd[r];
        else if (r < 2048) bv = bD[r - 1024];
        else if (r < 2064) bv = bb[r - 2048];
        else if (r < NCAT) bv = bc[r - 2064];
        g_bcat[r] = bv;
    }
    if (r < Dq && tid < Nq) {
        g_A2[r * Nq + tid] = -expf(logA[r * Nq + tid]) * 1.44269504088896340736f;
    }
}

/* ---------------- layernorm ---------------- */
__global__ void ln_kernel(const float* __restrict__ x,
                          const float* __restrict__ w,
                          const float* __restrict__ b)
{
    int row = blockIdx.x;
    int tid = threadIdx.x;
    const float4* x4 = reinterpret_cast<const float4*>(x) + (size_t)row * 256;
    float4 v = x4[tid];
    float sum = v.x + v.y + v.z + v.w;
    float sq  = v.x*v.x + v.y*v.y + v.z*v.z + v.w*v.w;

    #pragma unroll
    for (int o = 16; o > 0; o >>= 1) {
        sum += __shfl_down_sync(0xffffffffu, sum, o);
        sq  += __shfl_down_sync(0xffffffffu, sq, o);
    }
    __shared__ float red0[8], red1[8];
    int warp = tid >> 5, lane = tid & 31;
    if (lane == 0) { red0[warp] = sum; red1[warp] = sq; }
    __syncthreads();
    if (tid < 32) {
        float s1 = (tid < 8) ? red0[tid] : 0.f;
        float s2 = (tid < 8) ? red1[tid] : 0.f;
        #pragma unroll
        for (int o = 4; o > 0; o >>= 1) {
            s1 += __shfl_down_sync(0xffffffffu, s1, o);
            s2 += __shfl_down_sync(0xffffffffu, s2, o);
        }
        if (tid == 0) { red0[0] = s1; red1[0] = s2; }
    }
    __syncthreads();
    float mean = red0[0] * (1.0f / Dq);
    float var  = red1[0] * (1.0f / Dq) - mean * mean;
    float rs   = rsqrtf(var + 1e-5f);

    float4 wv = reinterpret_cast<const float4*>(w)[tid];
    float4 bv = reinterpret_cast<const float4*>(b)[tid];
    float4 o;
    o.x = (v.x - mean) * rs * wv.x + bv.x;
    o.y = (v.y - mean) * rs * wv.y + bv.y;
    o.z = (v.z - mean) * rs * wv.z + bv.z;
    o.w = (v.w - mean) * rs * wv.w + bv.w;
    reinterpret_cast<float4*>(g_h)[(size_t)row * 256 + tid] = o;

    __nv_bfloat16 hi[4], lo[4];
    float vv[4] = {o.x, o.y, o.z, o.w};
    #pragma unroll
    for (int i = 0; i < 4; i++) {
        hi[i] = __float2bfloat16(vv[i]);
        lo[i] = __float2bfloat16(vv[i] - __bfloat162float(hi[i]));
    }
    *reinterpret_cast<uint2*>(g_h_hi + (size_t)row * Kq + tid * 4) = *reinterpret_cast<uint2*>(hi);
    *reinterpret_cast<uint2*>(g_h_lo + (size_t)row * Kq + tid * 4) = *reinterpret_cast<uint2*>(lo);
}

/* =========== HMMA GEMM v2: BK=32, 3-stage cp.async, 1 sync/chunk =========== */
#define BK2 32
#define KPADB 80                  /* row stride bytes: 32 bf16 + 8 pad */
#define PLANEB (128 * KPADB)      /* 10240 B */
#define STAGEB (4 * PLANEB)       /* 40960 B */
#define NSTG 3
#define GSMEM (NSTG * STAGEB)     /* 122880 B */
#define NCHK2 (Kq / BK2)          /* 32 */

__device__ __forceinline__ void cp16(uint32_t dst, const void* src) {
    asm volatile("cp.async.cg.shared.global [%0], [%1], 16;" :: "r"(dst), "l"(src) : "memory");
}
__device__ __forceinline__ void cp_commit() {
    asm volatile("cp.async.commit_group;" ::: "memory");
}
template<int N> __device__ __forceinline__ void cp_wait() {
    asm volatile("cp.async.wait_group %0;" :: "n"(N) : "memory");
}
__device__ __forceinline__ void ldm_x4(uint32_t addr, uint32_t* r) {
    asm volatile("ldmatrix.sync.aligned.m8n8.x4.shared.b16 {%0,%1,%2,%3}, [%4];"
                 : "=r"(r[0]), "=r"(r[1]), "=r"(r[2]), "=r"(r[3]) : "r"(addr));
}
__device__ __forceinline__ void mma_bf16(float* c, const uint32_t* a, const uint32_t* b) {
    asm volatile("mma.sync.aligned.m16n8k16.row.col.f32.bf16.bf16.f32 "
                 "{%0,%1,%2,%3}, {%4,%5,%6,%7}, {%8,%9}, {%0,%1,%2,%3};"
                 : "+f"(c[0]), "+f"(c[1]), "+f"(c[2]), "+f"(c[3])
                 : "r"(a[0]), "r"(a[1]), "r"(a[2]), "r"(a[3]), "r"(b[0]), "r"(b[1]));
}
__device__ __forceinline__ float softplus_f(float v) {
    return fmaxf(v, 0.f) + log1pf(expf(-fabsf(v)));
}

__device__ __forceinline__ void fill_stage(uint32_t sbase, int kc, int tid,
                                           const __nv_bfloat16* Ah, const __nv_bfloat16* Al,
                                           const __nv_bfloat16* Bh, const __nv_bfloat16* Bl)
{
    const __nv_bfloat16* srcs[4] = {Ah, Al, Bh, Bl};
    #pragma unroll
    for (int p = 0; p < 4; p++) {
        #pragma unroll
        for (int i = 0; i < 2; i++) {
            int id = tid + i * 256;      /* 0..511 */
            int row = id >> 2, q = id & 3;
            cp16(sbase + p * PLANEB + row * KPADB + q * 16,
                 srcs[p] + (size_t)row * Kq + kc * BK2 + q * 8);
        }
    }
}

__global__ __launch_bounds__(256, 1)
void gemm_hmma_kernel()
{
    extern __shared__ __align__(16) char dynsm[];
    uint32_t smb = smem_u32(dynsm);

    int tid  = threadIdx.x;
    int wid  = tid >> 5, lane = tid & 31;
    int n0   = blockIdx.x * 128;
    int m0   = blockIdx.y * 128;
    int wm   = wid >> 1;
    int wn   = wid & 1;

    const __nv_bfloat16* Ah = g_h_hi + (size_t)m0 * Kq;
    const __nv_bfloat16* Al = g_h_lo + (size_t)m0 * Kq;
    const __nv_bfloat16* Bh = g_W_hi + (size_t)n0 * Kq;
    const __nv_bfloat16* Bl = g_W_lo + (size_t)n0 * Kq;

    float acc[2][8][4];
    #pragma unroll
    for (int i = 0; i < 2; i++)
        #pragma unroll
        for (int j = 0; j < 8; j++)
            #pragma unroll
            for (int k = 0; k < 4; k++) acc[i][j][k] = 0.f;

    /* precomputed ldmatrix row offsets (bytes within a plane) */
    uint32_t a_off[2], b_off[8];
    #pragma unroll
    for (int mt = 0; mt < 2; mt++)
        a_off[mt] = (uint32_t)((wm * 32 + (lane & 15) + mt * 16) * KPADB + (lane >> 4) * 16);
    #pragma unroll
    for (int p = 0; p < 4; p++)
        b_off[p] = (uint32_t)((wn * 64 + (lane & 7) + ((lane >> 4) * 8) + p * 16) * KPADB
                              + ((lane >> 3) & 1) * 16);

    /* prologue: stages 0,1 */
    fill_stage(smb + 0 * STAGEB, 0, tid, Ah, Al, Bh, Bl); cp_commit();
    fill_stage(smb + 1 * STAGEB, 1, tid, Ah, Al, Bh, Bl); cp_commit();

    for (int kc = 0; kc < NCHK2; kc++) {
        int buf = kc % NSTG;
        if (kc == NCHK2 - 1) cp_wait<0>(); else cp_wait<1>();
        __syncthreads();
        if (kc + 2 < NCHK2) {
            fill_stage(smb + ((kc + 2) % NSTG) * STAGEB, kc + 2, tid, Ah, Al, Bh, Bl);
            cp_commit();
        }

        uint32_t base = smb + buf * STAGEB;
        #pragma unroll
        for (int kk = 0; kk < 2; kk++) {
            uint32_t ko = (uint32_t)(kk * 32);
            uint32_t aH[2][4], aL[2][4], bHt[8][2], bLt[8][2];
            #pragma unroll
            for (int mt = 0; mt < 2; mt++) {
                ldm_x4(base + 0 * PLANEB + a_off[mt] + ko, aH[mt]);
                ldm_x4(base + 1 * PLANEB + a_off[mt] + ko, aL[mt]);
            }
            #pragma unroll
            for (int p = 0; p < 4; p++) {
                uint32_t r4[4];
                ldm_x4(base + 2 * PLANEB + b_off[p] + ko, r4);
                bHt[2*p][0] = r4[0]; bHt[2*p][1] = r4[1];
                bHt[2*p+1][0] = r4[2]; bHt[2*p+1][1] = r4[3];
                ldm_x4(base + 3 * PLANEB + b_off[p] + ko, r4);
                bLt[2*p][0] = r4[0]; bLt[2*p][1] = r4[1];
                bLt[2*p+1][0] = r4[2]; bLt[2*p+1][1] = r4[3];
            }
            #pragma unroll
            for (int mt = 0; mt < 2; mt++)
                #pragma unroll
                for (int nt = 0; nt < 8; nt++)
                    mma_bf16(acc[mt][nt], aH[mt], bHt[nt]);
            #pragma unroll
            for (int mt = 0; mt < 2; mt++)
                #pragma unroll
                for (int nt = 0; nt < 8; nt++)
                    mma_bf16(acc[mt][nt], aH[mt], bLt[nt]);
            #pragma unroll
            for (int mt = 0; mt < 2; mt++)
                #pragma unroll
                for (int nt = 0; nt < 8; nt++)
                    mma_bf16(acc[mt][nt], aL[mt], bHt[nt]);
        }
    }

    /* epilogue: routed stores */
    int qrow = lane >> 2;
    int qcol = (lane & 3) * 2;
    #pragma unroll
    for (int mt = 0; mt < 2; mt++) {
        #pragma unroll
        for (int half = 0; half < 2; half++) {
            int m = m0 + wm * 32 + mt * 16 + qrow + half * 8;
            #pragma unroll
            for (int nt = 0; nt < 8; nt++) {
                int col = n0 + wn * 64 + nt * 8 + qcol;
                if (col >= NCAT) continue;
                float v0 = acc[mt][nt][half * 2 + 0] + g_bcat[col];
                float v1 = acc[mt][nt][half * 2 + 1] + g_bcat[col + 1];
                if (col < 1024) {
                    *reinterpret_cast<float2*>(g_delta + (size_t)m * Dq + col) =
                        make_float2(softplus_f(v0), softplus_f(v1));
                } else if (col < 2048) {
                    *reinterpret_cast<float2*>(g_lin + (size_t)m * Dq + (col - 1024)) =
                        make_float2(v0, v1);
                } else if (col < 2064) {
                    *reinterpret_cast<float2*>(g_Bc + (size_t)m * Nq + (col - 2048)) =
                        make_float2(v0, v1);
                } else {
                    *reinterpret_cast<float2*>(g_Cc + (size_t)m * Nq + (col - 2064)) =
                        make_float2(v0, v1);
                }
            }
        }
    }
}

/* ------------- selective scan + residual; block = 4d x 16n ------------- */
__global__ __launch_bounds__(64)
void scan_kernel(const float* __restrict__ xin, float* __restrict__ out)
{
    int b    = blockIdx.y;
    int dblk = blockIdx.x;          /* 0..255 */
    int tid  = threadIdx.x;         /* 64 = 4 d x 16 n */
    int n    = tid & 15;
    int td   = tid >> 4;
    int d    = dblk * 4 + td;

    float a2 = g_A2[d * Nq + n];
    float s  = 0.f;

    int idx  = (b * Sq) * Dq + d;
    int nidx = (b * Sq) * Nq + n;

    float dt = g_delta[idx];
    float hh = g_h[idx];
    float bn = g_Bc[nidx];
    float cn = g_Cc[nidx];
    float xx = xin[idx];
    float ll = g_lin[idx];

    for (int t = 0; t < Sq; t++) {
        float dt1 = 0.f, hh1 = 0.f, bn1 = 0.f, cn1 = 0.f, xx1 = 0.f, ll1 = 0.f;
        int idx1 = idx + Dq, nidx1 = nidx + Nq;
        if (t < Sq - 1) {
            dt1 = g_delta[idx1];
            hh1 = g_h[idx1];
            bn1 = g_Bc[nidx1];
            cn1 = g_Cc[nidx1];
            xx1 = xin[idx1];
            ll1 = g_lin[idx1];
        }

        float dA = exp2f(dt * a2);
        s = fmaf(dA, s, dt * hh * bn);
        float p = s * cn;
        p += __shfl_xor_sync(0xffffffffu, p, 1);
        p += __shfl_xor_sync(0xffffffffu, p, 2);
        p += __shfl_xor_sync(0xffffffffu, p, 4);
        p += __shfl_xor_sync(0xffffffffu, p, 8);
        if (n == 0) out[idx] = xx + ll + p;

        dt = dt1; hh = hh1; bn = bn1; cn = cn1; xx = xx1; ll = ll1;
        idx = idx1; nidx = nidx1;
    }
}

/* ------------------------------- launch ------------------------------- */
extern "C" void kernel_launch(void* const* d_in, const int* in_sizes, int n_in,
                              void* d_out, int out_size)
{
    const float* x    = (const float*)d_in[0];
    const float* logA = (const float*)d_in[1];
    const float* Wd   = (const float*)d_in[2];
    const float* bd   = (const float*)d_in[3];
    const float* Wb   = (const float*)d_in[4];
    const float* bb   = (const float*)d_in[5];
    const float* Wc   = (const float*)d_in[6];
    const float* bc   = (const float*)d_in[7];
    const float* WDp  = (const float*)d_in[8];
    const float* bD   = (const float*)d_in[9];
    const float* lnw  = (const float*)d_in[10];
    const float* lnb  = (const float*)d_in[11];
    float* out = (float*)d_out;

    cudaFuncSetAttribute(gemm_hmma_kernel,
                         cudaFuncAttributeMaxDynamicSharedMemorySize, GSMEM);

    prep_kernel<<<NPAD, 256>>>(logA, Wd, bd, Wb, bb, Wc, bc, WDp, bD);
    ln_kernel<<<Mq, 256>>>(x, lnw, lnb);
    dim3 ggrid(NPAD / 128, Mq / 128);            /* 17 x 128 */
    gemm_hmma_kernel<<<ggrid, 256, GSMEM>>>();
    dim3 sgrid(Dq / 4, Bq);                      /* 256 x 4 */
    scan_kernel<<<sgrid, 64>>>(x, out);
}